// round 1
// baseline (speedup 1.0000x reference)
#include <cuda_runtime.h>
#include <math_constants.h>

// Problem dims (fixed by the dataset; derived defensively from in_sizes in kernel_launch)
#define DIM        256
#define MAX_V      4096
#define MAX_T      65536

// Main-kernel tiling
#define TM         64      // tokens per block
#define TC         128     // codes per tile
#define KC         32      // k chunk
#define NTHREADS   256
#define XS_STRIDE  68      // 64 + 4 pad (keeps float4 alignment: 68*4=272 % 16 == 0)
#define ES_STRIDE  132     // 128 + 4 pad (132*4=528 % 16 == 0)

// Scratch (device globals — no allocation allowed)
__device__ float g_e2[MAX_V];
__device__ float g_x2[MAX_T];
__device__ int   g_idx[MAX_T];
__device__ float g_partial[MAX_T / 4];   // 16384 block partials for the loss

// ---------------------------------------------------------------------------
// k1: e2[v] = sum_k emb[v,k]^2   (one warp per codebook row, deterministic order)
// ---------------------------------------------------------------------------
__global__ void k_e2(const float* __restrict__ emb, int V) {
    int w    = (blockIdx.x * blockDim.x + threadIdx.x) >> 5;
    int lane = threadIdx.x & 31;
    if (w >= V) return;
    const float* row = emb + (size_t)w * DIM;
    float s = 0.f;
    #pragma unroll
    for (int i = 0; i < DIM / 32; ++i) {
        float v = row[lane + i * 32];
        s = fmaf(v, v, s);
    }
    #pragma unroll
    for (int off = 16; off; off >>= 1) s += __shfl_xor_sync(0xffffffffu, s, off);
    if (lane == 0) g_e2[w] = s;
}

// ---------------------------------------------------------------------------
// k2: x2[t] = sum_k x[t,k]^2     (one warp per token)
// ---------------------------------------------------------------------------
__global__ void k_x2(const float* __restrict__ x, int T) {
    int w    = (blockIdx.x * blockDim.x + threadIdx.x) >> 5;
    int lane = threadIdx.x & 31;
    if (w >= T) return;
    const float* row = x + (size_t)w * DIM;
    float s = 0.f;
    #pragma unroll
    for (int i = 0; i < DIM / 32; ++i) {
        float v = row[lane + i * 32];
        s = fmaf(v, v, s);
    }
    #pragma unroll
    for (int off = 16; off; off >>= 1) s += __shfl_xor_sync(0xffffffffu, s, off);
    if (lane == 0) g_x2[w] = s;
}

// ---------------------------------------------------------------------------
// k3: fused distance-GEMM + argmin.
// Block: 256 threads = (tx in [0,16)) x (ty in [0,16)).
//   ty owns 4 consecutive tokens, tx owns 8 codes per tile (two float4 groups
//   at tx*4 and 64+tx*4 — keeps smem e-reads phase-conflict-free).
// d2 is computed EXACTLY as the reference: fl( fl(x2 + e2) - 2*xe ).
// Argmin: strict < within a thread (ascending code index), explicit
// lowest-index tie-break across threads.
// ---------------------------------------------------------------------------
__global__ void k_argmin(const float* __restrict__ x,
                         const float* __restrict__ emb,
                         int V) {
    extern __shared__ float sm[];
    float* xs   = sm;                          // [256][XS_STRIDE]
    float* es   = xs + DIM * XS_STRIDE;        // [KC][ES_STRIDE]
    float* redv = es + KC * ES_STRIDE;         // [TM][16]
    int*   redi = (int*)(redv + TM * 16);      // [TM][16]

    const int t    = threadIdx.x;
    const int tx   = t & 15;
    const int ty   = t >> 4;
    const int tok0 = blockIdx.x * TM;

    // ---- load x tile into smem, transposed to xs[k][token] ----
    #pragma unroll
    for (int i = 0; i < (TM * DIM / 4) / NTHREADS; ++i) {
        int f   = t + i * NTHREADS;            // f in [0, 4096)
        int tok = f >> 6;                      // 64 float4 per token
        int kq  = f & 63;
        float4 v = *(const float4*)(x + (size_t)(tok0 + tok) * DIM + kq * 4);
        xs[(kq * 4 + 0) * XS_STRIDE + tok] = v.x;
        xs[(kq * 4 + 1) * XS_STRIDE + tok] = v.y;
        xs[(kq * 4 + 2) * XS_STRIDE + tok] = v.z;
        xs[(kq * 4 + 3) * XS_STRIDE + tok] = v.w;
    }
    __syncthreads();

    float x2v[4];
    #pragma unroll
    for (int i = 0; i < 4; ++i) x2v[i] = g_x2[tok0 + ty * 4 + i];

    float minv[4];
    int   mini[4];
    #pragma unroll
    for (int i = 0; i < 4; ++i) { minv[i] = CUDART_INF_F; mini[i] = 0; }

    for (int ct = 0; ct < V / TC; ++ct) {
        const int c0 = ct * TC;
        float acc[4][8];
        #pragma unroll
        for (int i = 0; i < 4; ++i)
            #pragma unroll
            for (int j = 0; j < 8; ++j) acc[i][j] = 0.f;

        for (int kc = 0; kc < DIM / KC; ++kc) {
            __syncthreads();
            // load e chunk: TC codes x KC k, transposed to es[k][code]
            #pragma unroll
            for (int p = 0; p < (TC * KC / 4) / NTHREADS; ++p) {
                int f  = t + p * NTHREADS;     // f in [0, 1024)
                int cr = f >> 3;               // code row 0..127
                int kq = f & 7;                // float4 index along k
                float4 v = *(const float4*)(emb + (size_t)(c0 + cr) * DIM + kc * KC + kq * 4);
                es[(kq * 4 + 0) * ES_STRIDE + cr] = v.x;
                es[(kq * 4 + 1) * ES_STRIDE + cr] = v.y;
                es[(kq * 4 + 2) * ES_STRIDE + cr] = v.z;
                es[(kq * 4 + 3) * ES_STRIDE + cr] = v.w;
            }
            __syncthreads();

            #pragma unroll 8
            for (int k = 0; k < KC; ++k) {
                float4 xv = *(const float4*)(xs + (kc * KC + k) * XS_STRIDE + ty * 4);
                float4 ea = *(const float4*)(es + k * ES_STRIDE + tx * 4);
                float4 eb = *(const float4*)(es + k * ES_STRIDE + 64 + tx * 4);
                float xr[4] = {xv.x, xv.y, xv.z, xv.w};
                float er[8] = {ea.x, ea.y, ea.z, ea.w, eb.x, eb.y, eb.z, eb.w};
                #pragma unroll
                for (int i = 0; i < 4; ++i)
                    #pragma unroll
                    for (int j = 0; j < 8; ++j)
                        acc[i][j] = fmaf(xr[i], er[j], acc[i][j]);
            }
        }

        // epilogue: d2 + running argmin (codes ascending within thread)
        #pragma unroll
        for (int j = 0; j < 8; ++j) {
            int c = c0 + ((j < 4) ? (tx * 4 + j) : (64 + tx * 4 + (j - 4)));
            float e2c = g_e2[c];
            #pragma unroll
            for (int i = 0; i < 4; ++i) {
                float t2 = x2v[i] + e2c;                 // fl(x2 + e2)
                float d2 = fmaf(-2.0f, acc[i][j], t2);   // fl(t2 - 2*xe)
                if (d2 < minv[i]) { minv[i] = d2; mini[i] = c; }
            }
        }
    }

    // cross-tx reduction per token with lowest-index tie-break
    #pragma unroll
    for (int i = 0; i < 4; ++i) {
        redv[(ty * 4 + i) * 16 + tx] = minv[i];
        redi[(ty * 4 + i) * 16 + tx] = mini[i];
    }
    __syncthreads();
    if (t < TM) {
        float bv = redv[t * 16];
        int   bi = redi[t * 16];
        #pragma unroll
        for (int s = 1; s < 16; ++s) {
            float v = redv[t * 16 + s];
            int   ix = redi[t * 16 + s];
            if (v < bv || (v == bv && ix < bi)) { bv = v; bi = ix; }
        }
        g_idx[tok0 + t] = bi;
    }
}

// ---------------------------------------------------------------------------
// k4: gather + straight-through output + per-block loss partials.
// out[e] = fl( x + fl(emb[idx] - x) )  — exact ST expression.
// ---------------------------------------------------------------------------
__global__ void k_out(const float* __restrict__ x,
                      const float* __restrict__ emb,
                      float* __restrict__ out) {
    int base = blockIdx.x * 1024 + threadIdx.x;
    float s = 0.f;
    #pragma unroll
    for (int i = 0; i < 4; ++i) {
        int e    = base + i * 256;
        int tok  = e >> 8;
        int dpos = e & 255;
        float xv = x[e];
        float q  = emb[(size_t)g_idx[tok] * DIM + dpos];
        float d  = q - xv;
        out[e]   = xv + d;
        s = fmaf(d, d, s);
    }
    // deterministic block reduction (butterfly within warp, ordered across warps)
    #pragma unroll
    for (int off = 16; off; off >>= 1) s += __shfl_xor_sync(0xffffffffu, s, off);
    __shared__ float ws[8];
    int lane = threadIdx.x & 31, warp = threadIdx.x >> 5;
    if (lane == 0) ws[warp] = s;
    __syncthreads();
    if (threadIdx.x == 0) {
        float b = ws[0];
        #pragma unroll
        for (int w = 1; w < 8; ++w) b += ws[w];
        g_partial[blockIdx.x] = b;
    }
}

// ---------------------------------------------------------------------------
// k5: final loss = m + 0.25*m,  m = sum/N   (single block, fixed-order tree)
// ---------------------------------------------------------------------------
__global__ void k_loss(float* __restrict__ out, int N, int nPartial) {
    __shared__ float smem[256];
    float s = 0.f;
    for (int i = threadIdx.x; i < nPartial; i += 256) s += g_partial[i];
    smem[threadIdx.x] = s;
    __syncthreads();
    #pragma unroll
    for (int step = 128; step; step >>= 1) {
        if (threadIdx.x < step) smem[threadIdx.x] += smem[threadIdx.x + step];
        __syncthreads();
    }
    if (threadIdx.x == 0) {
        float m = smem[0] / (float)N;
        out[N] = m + 0.25f * m;
    }
}

// ---------------------------------------------------------------------------
extern "C" void kernel_launch(void* const* d_in, const int* in_sizes, int n_in,
                              void* d_out, int out_size) {
    const float* x   = (const float*)d_in[0];
    const float* emb = (const float*)d_in[1];
    float* out = (float*)d_out;

    const int T = in_sizes[0] / DIM;   // 65536
    const int V = in_sizes[1] / DIM;   // 4096
    const int N = T * DIM;             // 16777216

    // dynamic smem for the main kernel
    const int smem_bytes = (DIM * XS_STRIDE + KC * ES_STRIDE + TM * 16) * 4
                         + TM * 16 * 4;
    static bool attr_set = false;
    if (!attr_set) {
        cudaFuncSetAttribute(k_argmin, cudaFuncAttributeMaxDynamicSharedMemorySize,
                             smem_bytes);
        attr_set = true;
    }

    k_e2<<<(V + 7) / 8, NTHREADS>>>(emb, V);
    k_x2<<<(T + 7) / 8, NTHREADS>>>(x, T);
    k_argmin<<<T / TM, NTHREADS, smem_bytes>>>(x, emb, V);
    k_out<<<N / 1024, NTHREADS>>>(x, emb, out);
    if (out_size > N) {
        k_loss<<<1, 256>>>(out, N, N / 1024);
    }
}

// round 2
// speedup vs baseline: 1.0009x; 1.0009x over previous
#include <cuda_runtime.h>
#include <math_constants.h>

// Problem dims (fixed by the dataset; derived defensively from in_sizes in kernel_launch)
#define DIM        256
#define MAX_V      4096
#define MAX_T      65536

// Main-kernel tiling
#define TM         64      // tokens per block
#define TC         128     // codes per tile
#define KC         32      // k chunk
#define NTHREADS   256
#define XS_STRIDE  68      // 64 + 4 pad (keeps float4 alignment: 68*4=272 % 16 == 0)
#define ES_STRIDE  132     // 128 + 4 pad (132*4=528 % 16 == 0)

// Scratch (device globals — no allocation allowed)
__device__ float g_e2[MAX_V];
__device__ float g_x2[MAX_T];
__device__ int   g_idx[MAX_T];
__device__ float g_partial[MAX_T / 4];   // 16384 block partials for the loss

// ---------------------------------------------------------------------------
// k1: e2[v] = sum_k emb[v,k]^2   (one warp per codebook row, deterministic order)
// ---------------------------------------------------------------------------
__global__ void k_e2(const float* __restrict__ emb, int V) {
    int w    = (blockIdx.x * blockDim.x + threadIdx.x) >> 5;
    int lane = threadIdx.x & 31;
    if (w >= V) return;
    const float* row = emb + (size_t)w * DIM;
    float s = 0.f;
    #pragma unroll
    for (int i = 0; i < DIM / 32; ++i) {
        float v = row[lane + i * 32];
        s = fmaf(v, v, s);
    }
    #pragma unroll
    for (int off = 16; off; off >>= 1) s += __shfl_xor_sync(0xffffffffu, s, off);
    if (lane == 0) g_e2[w] = s;
}

// ---------------------------------------------------------------------------
// k2: x2[t] = sum_k x[t,k]^2     (one warp per token)
// ---------------------------------------------------------------------------
__global__ void k_x2(const float* __restrict__ x, int T) {
    int w    = (blockIdx.x * blockDim.x + threadIdx.x) >> 5;
    int lane = threadIdx.x & 31;
    if (w >= T) return;
    const float* row = x + (size_t)w * DIM;
    float s = 0.f;
    #pragma unroll
    for (int i = 0; i < DIM / 32; ++i) {
        float v = row[lane + i * 32];
        s = fmaf(v, v, s);
    }
    #pragma unroll
    for (int off = 16; off; off >>= 1) s += __shfl_xor_sync(0xffffffffu, s, off);
    if (lane == 0) g_x2[w] = s;
}

// ---------------------------------------------------------------------------
// k3: fused distance-GEMM + argmin.
// Block: 256 threads = (tx in [0,16)) x (ty in [0,16)).
//   ty owns 4 consecutive tokens, tx owns 8 codes per tile (two float4 groups
//   at tx*4 and 64+tx*4 — keeps smem e-reads phase-conflict-free).
// d2 is computed EXACTLY as the reference: fl( fl(x2 + e2) - 2*xe ).
// Argmin: strict < within a thread (ascending code index), explicit
// lowest-index tie-break across threads.
// ---------------------------------------------------------------------------
__global__ void k_argmin(const float* __restrict__ x,
                         const float* __restrict__ emb,
                         int V) {
    extern __shared__ float sm[];
    float* xs   = sm;                          // [256][XS_STRIDE]
    float* es   = xs + DIM * XS_STRIDE;        // [KC][ES_STRIDE]
    float* redv = es + KC * ES_STRIDE;         // [TM][16]
    int*   redi = (int*)(redv + TM * 16);      // [TM][16]

    const int t    = threadIdx.x;
    const int tx   = t & 15;
    const int ty   = t >> 4;
    const int tok0 = blockIdx.x * TM;

    // ---- load x tile into smem, transposed to xs[k][token] ----
    #pragma unroll
    for (int i = 0; i < (TM * DIM / 4) / NTHREADS; ++i) {
        int f   = t + i * NTHREADS;            // f in [0, 4096)
        int tok = f >> 6;                      // 64 float4 per token
        int kq  = f & 63;
        float4 v = *(const float4*)(x + (size_t)(tok0 + tok) * DIM + kq * 4);
        xs[(kq * 4 + 0) * XS_STRIDE + tok] = v.x;
        xs[(kq * 4 + 1) * XS_STRIDE + tok] = v.y;
        xs[(kq * 4 + 2) * XS_STRIDE + tok] = v.z;
        xs[(kq * 4 + 3) * XS_STRIDE + tok] = v.w;
    }
    __syncthreads();

    float x2v[4];
    #pragma unroll
    for (int i = 0; i < 4; ++i) x2v[i] = g_x2[tok0 + ty * 4 + i];

    float minv[4];
    int   mini[4];
    #pragma unroll
    for (int i = 0; i < 4; ++i) { minv[i] = CUDART_INF_F; mini[i] = 0; }

    for (int ct = 0; ct < V / TC; ++ct) {
        const int c0 = ct * TC;
        float acc[4][8];
        #pragma unroll
        for (int i = 0; i < 4; ++i)
            #pragma unroll
            for (int j = 0; j < 8; ++j) acc[i][j] = 0.f;

        for (int kc = 0; kc < DIM / KC; ++kc) {
            __syncthreads();
            // load e chunk: TC codes x KC k, transposed to es[k][code]
            #pragma unroll
            for (int p = 0; p < (TC * KC / 4) / NTHREADS; ++p) {
                int f  = t + p * NTHREADS;     // f in [0, 1024)
                int cr = f >> 3;               // code row 0..127
                int kq = f & 7;                // float4 index along k
                float4 v = *(const float4*)(emb + (size_t)(c0 + cr) * DIM + kc * KC + kq * 4);
                es[(kq * 4 + 0) * ES_STRIDE + cr] = v.x;
                es[(kq * 4 + 1) * ES_STRIDE + cr] = v.y;
                es[(kq * 4 + 2) * ES_STRIDE + cr] = v.z;
                es[(kq * 4 + 3) * ES_STRIDE + cr] = v.w;
            }
            __syncthreads();

            #pragma unroll 8
            for (int k = 0; k < KC; ++k) {
                float4 xv = *(const float4*)(xs + (kc * KC + k) * XS_STRIDE + ty * 4);
                float4 ea = *(const float4*)(es + k * ES_STRIDE + tx * 4);
                float4 eb = *(const float4*)(es + k * ES_STRIDE + 64 + tx * 4);
                float xr[4] = {xv.x, xv.y, xv.z, xv.w};
                float er[8] = {ea.x, ea.y, ea.z, ea.w, eb.x, eb.y, eb.z, eb.w};
                #pragma unroll
                for (int i = 0; i < 4; ++i)
                    #pragma unroll
                    for (int j = 0; j < 8; ++j)
                        acc[i][j] = fmaf(xr[i], er[j], acc[i][j]);
            }
        }

        // epilogue: d2 + running argmin (codes ascending within thread)
        #pragma unroll
        for (int j = 0; j < 8; ++j) {
            int c = c0 + ((j < 4) ? (tx * 4 + j) : (64 + tx * 4 + (j - 4)));
            float e2c = g_e2[c];
            #pragma unroll
            for (int i = 0; i < 4; ++i) {
                float t2 = x2v[i] + e2c;                 // fl(x2 + e2)
                float d2 = fmaf(-2.0f, acc[i][j], t2);   // fl(t2 - 2*xe)
                if (d2 < minv[i]) { minv[i] = d2; mini[i] = c; }
            }
        }
    }

    // cross-tx reduction per token with lowest-index tie-break
    #pragma unroll
    for (int i = 0; i < 4; ++i) {
        redv[(ty * 4 + i) * 16 + tx] = minv[i];
        redi[(ty * 4 + i) * 16 + tx] = mini[i];
    }
    __syncthreads();
    if (t < TM) {
        float bv = redv[t * 16];
        int   bi = redi[t * 16];
        #pragma unroll
        for (int s = 1; s < 16; ++s) {
            float v = redv[t * 16 + s];
            int   ix = redi[t * 16 + s];
            if (v < bv || (v == bv && ix < bi)) { bv = v; bi = ix; }
        }
        g_idx[tok0 + t] = bi;
    }
}

// ---------------------------------------------------------------------------
// k4: gather + straight-through output + per-block loss partials.
// out[e] = fl( x + fl(emb[idx] - x) )  — exact ST expression.
// ---------------------------------------------------------------------------
__global__ void k_out(const float* __restrict__ x,
                      const float* __restrict__ emb,
                      float* __restrict__ out) {
    int base = blockIdx.x * 1024 + threadIdx.x;
    float s = 0.f;
    #pragma unroll
    for (int i = 0; i < 4; ++i) {
        int e    = base + i * 256;
        int tok  = e >> 8;
        int dpos = e & 255;
        float xv = x[e];
        float q  = emb[(size_t)g_idx[tok] * DIM + dpos];
        float d  = q - xv;
        out[e]   = xv + d;
        s = fmaf(d, d, s);
    }
    // deterministic block reduction (butterfly within warp, ordered across warps)
    #pragma unroll
    for (int off = 16; off; off >>= 1) s += __shfl_xor_sync(0xffffffffu, s, off);
    __shared__ float ws[8];
    int lane = threadIdx.x & 31, warp = threadIdx.x >> 5;
    if (lane == 0) ws[warp] = s;
    __syncthreads();
    if (threadIdx.x == 0) {
        float b = ws[0];
        #pragma unroll
        for (int w = 1; w < 8; ++w) b += ws[w];
        g_partial[blockIdx.x] = b;
    }
}

// ---------------------------------------------------------------------------
// k5: final loss = m + 0.25*m,  m = sum/N   (single block, fixed-order tree)
// ---------------------------------------------------------------------------
__global__ void k_loss(float* __restrict__ out, int N, int nPartial) {
    __shared__ float smem[256];
    float s = 0.f;
    for (int i = threadIdx.x; i < nPartial; i += 256) s += g_partial[i];
    smem[threadIdx.x] = s;
    __syncthreads();
    #pragma unroll
    for (int step = 128; step; step >>= 1) {
        if (threadIdx.x < step) smem[threadIdx.x] += smem[threadIdx.x + step];
        __syncthreads();
    }
    if (threadIdx.x == 0) {
        float m = smem[0] / (float)N;
        out[N] = m + 0.25f * m;
    }
}

// ---------------------------------------------------------------------------
extern "C" void kernel_launch(void* const* d_in, const int* in_sizes, int n_in,
                              void* d_out, int out_size) {
    const float* x   = (const float*)d_in[0];
    const float* emb = (const float*)d_in[1];
    float* out = (float*)d_out;

    const int T = in_sizes[0] / DIM;   // 65536
    const int V = in_sizes[1] / DIM;   // 4096
    const int N = T * DIM;             // 16777216

    // dynamic smem for the main kernel
    const int smem_bytes = (DIM * XS_STRIDE + KC * ES_STRIDE + TM * 16) * 4
                         + TM * 16 * 4;
    static bool attr_set = false;
    if (!attr_set) {
        cudaFuncSetAttribute(k_argmin, cudaFuncAttributeMaxDynamicSharedMemorySize,
                             smem_bytes);
        attr_set = true;
    }

    k_e2<<<(V + 7) / 8, NTHREADS>>>(emb, V);
    k_x2<<<(T + 7) / 8, NTHREADS>>>(x, T);
    k_argmin<<<T / TM, NTHREADS, smem_bytes>>>(x, emb, V);
    k_out<<<N / 1024, NTHREADS>>>(x, emb, out);
    if (out_size > N) {
        k_loss<<<1, 256>>>(out, N, N / 1024);
    }
}

// round 6
// speedup vs baseline: 2.7368x; 2.7343x over previous
#include <cuda_runtime.h>
#include <math_constants.h>
#include <cstdint>

#define DIMK  256
#define NV    4096
#define NT    65536
#define MT    128          // tokens per block
#define NTHR  256

// smem layout (float offsets)
#define SM_E2  0           // 4096
#define SM_A   4096        // 32768 (A tf32, fragment lane order)
#define SM_B   36864       // 2 stages x 4096 (tf32 B)
#define SMEMF  45056       // 180224 bytes

__device__ float g_e2[NV];
__device__ float g_x2[NT];
__device__ int   g_idx[NT];
__device__ float g_partial[16384];
__device__ float g_bh[NV * DIMK];     // emb tf32, blocked fragment order
__device__ int   g_ci[NT * 8];        // top-6 candidates per token (padded to 8)

__device__ __forceinline__ uint32_t s2u(const void* p) {
    uint32_t a;
    asm("{ .reg .u64 t; cvta.to.shared.u64 t, %1; cvt.u32.u64 %0, t; }" : "=r"(a) : "l"(p));
    return a;
}
__device__ __forceinline__ float tf32r(float a) {
    uint32_t u; asm("cvt.rna.tf32.f32 %0, %1;" : "=r"(u) : "f"(a));
    return __uint_as_float(u);
}
__device__ __forceinline__ void cp16(uint32_t d, const void* s) {
    asm volatile("cp.async.cg.shared.global [%0], [%1], 16;" :: "r"(d), "l"(s));
}
#define CP_COMMIT() asm volatile("cp.async.commit_group;" ::: "memory")
#define CP_WAIT1()  asm volatile("cp.async.wait_group 1;" ::: "memory")
#define CP_WAIT0()  asm volatile("cp.async.wait_group 0;" ::: "memory")

#define MMA(c, a, b) asm volatile(                                         \
    "mma.sync.aligned.m16n8k8.row.col.f32.tf32.tf32.f32 "                  \
    "{%0,%1,%2,%3}, {%4,%5,%6,%7}, {%8,%9}, {%0,%1,%2,%3};"                \
    : "+f"((c)[0]), "+f"((c)[1]), "+f"((c)[2]), "+f"((c)[3])               \
    : "r"((a)[0]), "r"((a)[1]), "r"((a)[2]), "r"((a)[3]),                  \
      "r"((b)[0]), "r"((b)[1]))

// -------------------- row sums of squares --------------------
__global__ void k_e2(const float* __restrict__ emb) {
    int w = (blockIdx.x * blockDim.x + threadIdx.x) >> 5, l = threadIdx.x & 31;
    if (w >= NV) return;
    const float* r = emb + (size_t)w * DIMK;
    float s = 0.f;
    #pragma unroll
    for (int i = 0; i < 8; ++i) { float v = r[l + i * 32]; s = fmaf(v, v, s); }
    #pragma unroll
    for (int o = 16; o; o >>= 1) s += __shfl_xor_sync(~0u, s, o);
    if (l == 0) g_e2[w] = s;
}
__global__ void k_x2(const float* __restrict__ x) {
    int w = (blockIdx.x * blockDim.x + threadIdx.x) >> 5, l = threadIdx.x & 31;
    if (w >= NT) return;
    const float* r = x + (size_t)w * DIMK;
    float s = 0.f;
    #pragma unroll
    for (int i = 0; i < 8; ++i) { float v = r[l + i * 32]; s = fmaf(v, v, s); }
    #pragma unroll
    for (int o = 16; o; o >>= 1) s += __shfl_xor_sync(~0u, s, o);
    if (l == 0) g_x2[w] = s;
}

// -------- pre-convert emb to tf32 in blocked mma-fragment order --------
// slot = (((n>>7)*8 + (k>>5))*4 + ((k>>3)&3))*16 + ((n>>3)&15)
// dst  = slot*64 + (((n&7)<<2)|(k&3))*2 + ((k>>2)&1)
__global__ void k_bsplit(const float* __restrict__ emb) {
    int i = blockIdx.x * NTHR + threadIdx.x;
    int n = i >> 8, k = i & 255;
    float h = tf32r(emb[i]);
    int slot = ((((n >> 7) * 8 + (k >> 5)) * 4 + ((k >> 3) & 3)) * 16 + ((n >> 3) & 15));
    int dst  = slot * 64 + ((((n & 7) << 2) | (k & 3)) << 1) + ((k >> 2) & 1);
    g_bh[dst] = h;
}

// ------------- main: tf32 mma ranking GEMM + top-2/thread + top-6/token -------------
__global__ void __launch_bounds__(NTHR, 1)
k_gemm(const float* __restrict__ x) {
    extern __shared__ float sm[];
    const int tid = threadIdx.x, lane = tid & 31, wid = tid >> 5;
    const int wm = wid >> 2, wn = wid & 3;          // warp grid 2(M) x 4(N)
    const int tok0 = blockIdx.x * MT;
    const uint32_t sb = s2u(sm);

    for (int i = tid; i < NV; i += NTHR) sm[SM_E2 + i] = g_e2[i];

    // A -> smem as tf32, mma-A-fragment lane order
    for (int f = tid; f < MT * DIMK / 4; f += NTHR) {
        int m = f >> 6, k0 = (f & 63) << 2;
        float4 v = *(const float4*)(x + (size_t)(tok0 + m) * DIMK + k0);
        float vv[4] = {v.x, v.y, v.z, v.w};
        #pragma unroll
        for (int j = 0; j < 4; ++j) {
            int kk = k0 + j;
            int slot = (kk >> 3) * 8 + (m >> 4);
            int r = m & 15;
            int ln = ((r & 7) << 2) | (kk & 3);
            int rg = ((r >> 3) & 1) | (((kk >> 2) & 1) << 1);
            sm[SM_A + slot * 128 + ln * 4 + rg] = tf32r(vv[j]);
        }
    }
    __syncthreads();

    float v1[8], v2[8]; int i1[8], i2[8];
    #pragma unroll
    for (int s = 0; s < 8; ++s) {
        v1[s] = CUDART_INF_F; v2[s] = CUDART_INF_F;
        i1[s] = 0x7fffffff;   i2[s] = 0x7fffffff;
    }

    // prefetch stage 0
    {
        uint32_t db = sb + SM_B * 4;
        for (int t2 = tid; t2 < 1024; t2 += NTHR) cp16(db + t2 * 16, g_bh + t2 * 4);
        CP_COMMIT();
    }

    float C[4][4][4];

    for (int id = 0; id < 256; ++id) {          // id = nt*8 + kc, nt<32, kc<8
        const int buf = id & 1, kc = id & 7;
        if (kc == 0) {
            #pragma unroll
            for (int a = 0; a < 4; ++a)
                #pragma unroll
                for (int b = 0; b < 4; ++b)
                    #pragma unroll
                    for (int q = 0; q < 4; ++q) C[a][b][q] = 0.f;
        }
        if (id + 1 < 256) {
            const float* sh = g_bh + (size_t)(id + 1) * 4096;
            uint32_t db = sb + (SM_B + (buf ^ 1) * 4096) * 4;
            for (int t2 = tid; t2 < 1024; t2 += NTHR) cp16(db + t2 * 16, sh + t2 * 4);
            CP_COMMIT();
            CP_WAIT1();
        } else {
            CP_WAIT0();
        }
        __syncthreads();

        const float* bs = sm + SM_B + buf * 4096;
        #pragma unroll
        for (int ks = 0; ks < 4; ++ks) {
            uint32_t ah[4][4];
            #pragma unroll
            for (int fm = 0; fm < 4; ++fm) {
                int slot = (kc * 4 + ks) * 8 + wm * 4 + fm;
                float4 ra = *(const float4*)&sm[SM_A + slot * 128 + lane * 4];
                ah[fm][0] = __float_as_uint(ra.x); ah[fm][1] = __float_as_uint(ra.y);
                ah[fm][2] = __float_as_uint(ra.z); ah[fm][3] = __float_as_uint(ra.w);
            }
            uint32_t bh[4][2];
            #pragma unroll
            for (int fn = 0; fn < 4; ++fn) {
                int off = (ks * 16 + wn * 4 + fn) * 64 + lane * 2;
                float2 h2 = *(const float2*)&bs[off];
                bh[fn][0] = __float_as_uint(h2.x); bh[fn][1] = __float_as_uint(h2.y);
            }
            #pragma unroll
            for (int fm = 0; fm < 4; ++fm)
                #pragma unroll
                for (int fn = 0; fn < 4; ++fn) MMA(C[fm][fn], ah[fm], bh[fn]);
        }

        if (kc == 7) {
            // ranking value: e2[c] - 2*xe  (x2 constant per row, irrelevant to rank)
            const int nt = id >> 3;
            #pragma unroll
            for (int fn = 0; fn < 4; ++fn)
                #pragma unroll
                for (int fm = 0; fm < 4; ++fm)
                    #pragma unroll
                    for (int q = 0; q < 4; ++q) {
                        int s = (fm << 1) | (q >> 1);
                        int col = nt * 128 + wn * 32 + fn * 8 + (lane & 3) * 2 + (q & 1);
                        float d = fmaf(-2.0f, C[fm][fn][q], sm[SM_E2 + col]);
                        if (d < v1[s]) { v2[s] = v1[s]; i2[s] = i1[s]; v1[s] = d; i1[s] = col; }
                        else if (d < v2[s]) { v2[s] = d; i2[s] = col; }
                    }
        }
        __syncthreads();
    }

    // dump per-thread top-2 (16 contributors x 2 per token) into smem (reuse B region)
    float* rv = sm + SM_B;                 // [128][32]
    int*   ri = (int*)(sm + SM_B + 4096);  // [128][32]
    #pragma unroll
    for (int s = 0; s < 8; ++s) {
        int row  = wm * 64 + (s >> 1) * 16 + (lane >> 2) + (s & 1) * 8;
        int base = row * 32 + (wn * 4 + (lane & 3)) * 2;
        rv[base] = v1[s]; ri[base] = i1[s];
        rv[base + 1] = v2[s]; ri[base + 1] = i2[s];
    }
    __syncthreads();
    // per-token top-6 by lex (v, idx)
    if (tid < MT) {
        #pragma unroll
        for (int j = 0; j < 6; ++j) {
            float bv = CUDART_INF_F; int bi = 0x7fffffff, bk = 0;
            for (int k = 0; k < 32; ++k) {
                float v = rv[tid * 32 + k]; int ix = ri[tid * 32 + k];
                if (v < bv || (v == bv && ix < bi)) { bv = v; bi = ix; bk = k; }
            }
            rv[tid * 32 + bk] = CUDART_INF_F;
            ri[tid * 32 + bk] = 0x7fffffff;
            g_ci[(size_t)(tok0 + tid) * 8 + j] = bi;
        }
    }
}

// -------- exact fp32 rescore of 6 candidates/token (reference semantics) --------
__global__ void k_rescore(const float* __restrict__ x, const float* __restrict__ emb) {
    int t = blockIdx.x * 8 + (threadIdx.x >> 5);
    int lane = threadIdx.x & 31;
    const float* xr = x + (size_t)t * DIMK;
    float xl[8];
    #pragma unroll
    for (int i = 0; i < 8; ++i) xl[i] = xr[lane + i * 32];
    float x2v = g_x2[t];
    float bv = CUDART_INF_F; int bi = 0x7fffffff;
    #pragma unroll
    for (int j = 0; j < 6; ++j) {
        int c = g_ci[(size_t)t * 8 + j];
        const float* er = emb + (size_t)c * DIMK;
        float s = 0.f;
        #pragma unroll
        for (int i = 0; i < 8; ++i) s = fmaf(xl[i], er[lane + i * 32], s);
        #pragma unroll
        for (int o = 16; o; o >>= 1) s += __shfl_xor_sync(~0u, s, o);
        float d2 = fmaf(-2.0f, s, x2v + g_e2[c]);     // exact reference expression
        if (d2 < bv || (d2 == bv && c < bi)) { bv = d2; bi = c; }
    }
    if (lane == 0) g_idx[t] = bi;
}

// -------------------- gather + ST output + loss partials --------------------
__global__ void k_out(const float* __restrict__ x, const float* __restrict__ emb,
                      float* __restrict__ out) {
    int e4 = blockIdx.x * NTHR + threadIdx.x;
    int tok = e4 >> 6;
    float4 xv = ((const float4*)x)[e4];
    float4 qv = ((const float4*)emb)[(size_t)g_idx[tok] * 64 + (e4 & 63)];
    float dx = qv.x - xv.x, dy = qv.y - xv.y, dz = qv.z - xv.z, dw = qv.w - xv.w;
    float4 ov = {xv.x + dx, xv.y + dy, xv.z + dz, xv.w + dw};
    ((float4*)out)[e4] = ov;
    float s = fmaf(dx, dx, fmaf(dy, dy, fmaf(dz, dz, dw * dw)));
    #pragma unroll
    for (int o = 16; o; o >>= 1) s += __shfl_xor_sync(~0u, s, o);
    __shared__ float ws[8];
    if ((threadIdx.x & 31) == 0) ws[threadIdx.x >> 5] = s;
    __syncthreads();
    if (threadIdx.x == 0) {
        float b = ws[0];
        #pragma unroll
        for (int w = 1; w < 8; ++w) b += ws[w];
        g_partial[blockIdx.x] = b;
    }
}

__global__ void k_loss(float* __restrict__ out, int N, int nP) {
    __shared__ float s2[256];
    float s = 0.f;
    for (int i = threadIdx.x; i < nP; i += 256) s += g_partial[i];
    s2[threadIdx.x] = s;
    __syncthreads();
    #pragma unroll
    for (int st = 128; st; st >>= 1) {
        if (threadIdx.x < st) s2[threadIdx.x] += s2[threadIdx.x + st];
        __syncthreads();
    }
    if (threadIdx.x == 0) { float m = s2[0] / (float)N; out[N] = m + 0.25f * m; }
}

// ---------------------------------------------------------------------------
extern "C" void kernel_launch(void* const* d_in, const int* in_sizes, int n_in,
                              void* d_out, int out_size) {
    const float* x   = (const float*)d_in[0];
    const float* emb = (const float*)d_in[1];
    float* out = (float*)d_out;
    const int N = NT * DIMK;

    static bool init = false;
    if (!init) {
        cudaFuncSetAttribute(k_gemm, cudaFuncAttributeMaxDynamicSharedMemorySize,
                             SMEMF * 4);
        init = true;
    }
    k_e2<<<NV / 8, NTHR>>>(emb);
    k_x2<<<NT / 8, NTHR>>>(x);
    k_bsplit<<<NV * DIMK / NTHR, NTHR>>>(emb);
    k_gemm<<<NT / MT, NTHR, SMEMF * 4>>>(x);
    k_rescore<<<NT / 8, NTHR>>>(x, emb);
    k_out<<<N / 4 / NTHR, NTHR>>>(x, emb, out);
    k_loss<<<1, 256>>>(out, N, N / 4 / NTHR);
}

// round 7
// speedup vs baseline: 3.3272x; 1.2157x over previous
#include <cuda_runtime.h>
#include <math_constants.h>
#include <cstdint>

#define DIMK  256
#define NV    4096
#define NT    65536
#define MT    64           // tokens per block
#define NTHR  256

// smem layout (float offsets) — 98304 bytes total => 2 CTAs/SM
#define SM_A   0           // 16384 floats (A tf32, fragment lane order)
#define SM_B   16384       // 2 stages x 4096 floats (tf32 B)
#define SMEMF  24576

__device__ float g_e2[NV];
__device__ float g_x2[NT];
__device__ int   g_idx[NT];
__device__ float g_partial[16384];
__device__ float g_bh[NV * DIMK];     // emb tf32, blocked fragment order
__device__ int   g_ci[NT * 8];        // top-6 candidates per token (padded to 8)

__device__ __forceinline__ uint32_t s2u(const void* p) {
    uint32_t a;
    asm("{ .reg .u64 t; cvta.to.shared.u64 t, %1; cvt.u32.u64 %0, t; }" : "=r"(a) : "l"(p));
    return a;
}
__device__ __forceinline__ float tf32r(float a) {
    uint32_t u; asm("cvt.rna.tf32.f32 %0, %1;" : "=r"(u) : "f"(a));
    return __uint_as_float(u);
}
__device__ __forceinline__ void cp16(uint32_t d, const void* s) {
    asm volatile("cp.async.cg.shared.global [%0], [%1], 16;" :: "r"(d), "l"(s));
}
#define CP_COMMIT() asm volatile("cp.async.commit_group;" ::: "memory")
#define CP_WAIT1()  asm volatile("cp.async.wait_group 1;" ::: "memory")
#define CP_WAIT0()  asm volatile("cp.async.wait_group 0;" ::: "memory")

#define MMA(c, a, b) asm volatile(                                         \
    "mma.sync.aligned.m16n8k8.row.col.f32.tf32.tf32.f32 "                  \
    "{%0,%1,%2,%3}, {%4,%5,%6,%7}, {%8,%9}, {%0,%1,%2,%3};"                \
    : "+f"((c)[0]), "+f"((c)[1]), "+f"((c)[2]), "+f"((c)[3])               \
    : "r"((a)[0]), "r"((a)[1]), "r"((a)[2]), "r"((a)[3]),                  \
      "r"((b)[0]), "r"((b)[1]))

// -------------------- row sums of squares --------------------
__global__ void k_e2(const float* __restrict__ emb) {
    int w = (blockIdx.x * blockDim.x + threadIdx.x) >> 5, l = threadIdx.x & 31;
    if (w >= NV) return;
    const float* r = emb + (size_t)w * DIMK;
    float s = 0.f;
    #pragma unroll
    for (int i = 0; i < 8; ++i) { float v = r[l + i * 32]; s = fmaf(v, v, s); }
    #pragma unroll
    for (int o = 16; o; o >>= 1) s += __shfl_xor_sync(~0u, s, o);
    if (l == 0) g_e2[w] = s;
}
__global__ void k_x2(const float* __restrict__ x) {
    int w = (blockIdx.x * blockDim.x + threadIdx.x) >> 5, l = threadIdx.x & 31;
    if (w >= NT) return;
    const float* r = x + (size_t)w * DIMK;
    float s = 0.f;
    #pragma unroll
    for (int i = 0; i < 8; ++i) { float v = r[l + i * 32]; s = fmaf(v, v, s); }
    #pragma unroll
    for (int o = 16; o; o >>= 1) s += __shfl_xor_sync(~0u, s, o);
    if (l == 0) g_x2[w] = s;
}

// -------- pre-convert emb to tf32 in blocked mma-fragment order --------
// slot = (((n>>7)*8 + (k>>5))*4 + ((k>>3)&3))*16 + ((n>>3)&15)
// dst  = slot*64 + (((n&7)<<2)|(k&3))*2 + ((k>>2)&1)
__global__ void k_bsplit(const float* __restrict__ emb) {
    int i = blockIdx.x * NTHR + threadIdx.x;
    int n = i >> 8, k = i & 255;
    float h = tf32r(emb[i]);
    int slot = ((((n >> 7) * 8 + (k >> 5)) * 4 + ((k >> 3) & 3)) * 16 + ((n >> 3) & 15));
    int dst  = slot * 64 + ((((n & 7) << 2) | (k & 3)) << 1) + ((k >> 2) & 1);
    g_bh[dst] = h;
}

// ------------- main: tf32 mma ranking GEMM + top-2/thread + top-6/token -------------
// MT=64 tokens/CTA; 8 warps = 2(M) x 4(N); warp M-tile 32 rows (fm<2), N-tile 32 cols.
__global__ void __launch_bounds__(NTHR, 2)
k_gemm(const float* __restrict__ x) {
    extern __shared__ float sm[];
    const int tid = threadIdx.x, lane = tid & 31, wid = tid >> 5;
    const int wm = wid >> 2, wn = wid & 3;
    const int tok0 = blockIdx.x * MT;
    const uint32_t sb = s2u(sm);

    // A -> smem as tf32, mma-A-fragment lane order:
    // slot = (k>>3)*4 + (m>>4); within: lane=((m&15&7)<<2)|(k&3), reg=((m>>3)&1)|(((k>>2)&1)<<1)
    for (int f = tid; f < MT * DIMK / 4; f += NTHR) {
        int m = f >> 6, k0 = (f & 63) << 2;
        float4 v = *(const float4*)(x + (size_t)(tok0 + m) * DIMK + k0);
        float vv[4] = {v.x, v.y, v.z, v.w};
        #pragma unroll
        for (int j = 0; j < 4; ++j) {
            int kk = k0 + j;
            int slot = (kk >> 3) * 4 + (m >> 4);
            int r = m & 15;
            int ln = ((r & 7) << 2) | (kk & 3);
            int rg = ((r >> 3) & 1) | (((kk >> 2) & 1) << 1);
            sm[SM_A + slot * 128 + ln * 4 + rg] = tf32r(vv[j]);
        }
    }
    __syncthreads();

    float v1[4], v2[4]; int i1[4], i2[4];
    #pragma unroll
    for (int s = 0; s < 4; ++s) {
        v1[s] = CUDART_INF_F; v2[s] = CUDART_INF_F;
        i1[s] = 0x7fffffff;   i2[s] = 0x7fffffff;
    }

    // prefetch stage 0
    {
        uint32_t db = sb + SM_B * 4;
        for (int t2 = tid; t2 < 1024; t2 += NTHR) cp16(db + t2 * 16, g_bh + t2 * 4);
        CP_COMMIT();
    }

    float C[2][4][4];

    for (int id = 0; id < 256; ++id) {          // id = nt*8 + kc, nt<32, kc<8
        const int buf = id & 1, kc = id & 7;
        if (kc == 0) {
            #pragma unroll
            for (int a = 0; a < 2; ++a)
                #pragma unroll
                for (int b = 0; b < 4; ++b)
                    #pragma unroll
                    for (int q = 0; q < 4; ++q) C[a][b][q] = 0.f;
        }
        if (id + 1 < 256) {
            const float* sh = g_bh + (size_t)(id + 1) * 4096;
            uint32_t db = sb + (SM_B + (buf ^ 1) * 4096) * 4;
            for (int t2 = tid; t2 < 1024; t2 += NTHR) cp16(db + t2 * 16, sh + t2 * 4);
            CP_COMMIT();
            CP_WAIT1();
        } else {
            CP_WAIT0();
        }
        __syncthreads();

        const float* bs = sm + SM_B + buf * 4096;
        #pragma unroll
        for (int ks = 0; ks < 4; ++ks) {
            uint32_t ah[2][4];
            #pragma unroll
            for (int fm = 0; fm < 2; ++fm) {
                int slot = (kc * 4 + ks) * 4 + wm * 2 + fm;
                float4 ra = *(const float4*)&sm[SM_A + slot * 128 + lane * 4];
                ah[fm][0] = __float_as_uint(ra.x); ah[fm][1] = __float_as_uint(ra.y);
                ah[fm][2] = __float_as_uint(ra.z); ah[fm][3] = __float_as_uint(ra.w);
            }
            uint32_t bh[4][2];
            #pragma unroll
            for (int fn = 0; fn < 4; ++fn) {
                int off = (ks * 16 + wn * 4 + fn) * 64 + lane * 2;
                float2 h2 = *(const float2*)&bs[off];
                bh[fn][0] = __float_as_uint(h2.x); bh[fn][1] = __float_as_uint(h2.y);
            }
            #pragma unroll
            for (int fm = 0; fm < 2; ++fm)
                #pragma unroll
                for (int fn = 0; fn < 4; ++fn) MMA(C[fm][fn], ah[fm], bh[fn]);
        }

        if (kc == 7) {
            // ranking value: e2[c] - 2*xe  (x2 constant per row, irrelevant to rank)
            const int nt = id >> 3;
            #pragma unroll
            for (int fn = 0; fn < 4; ++fn)
                #pragma unroll
                for (int fm = 0; fm < 2; ++fm)
                    #pragma unroll
                    for (int q = 0; q < 4; ++q) {
                        int s = (fm << 1) | (q >> 1);
                        int col = nt * 128 + wn * 32 + fn * 8 + (lane & 3) * 2 + (q & 1);
                        float d = fmaf(-2.0f, C[fm][fn][q], __ldg(&g_e2[col]));
                        if (d < v1[s]) { v2[s] = v1[s]; i2[s] = i1[s]; v1[s] = d; i1[s] = col; }
                        else if (d < v2[s]) { v2[s] = d; i2[s] = col; }
                    }
        }
        __syncthreads();
    }

    // dump per-thread top-2 (16 contributors x 2 per token) into smem (reuse B region)
    float* rv = sm + SM_B;                 // [64][32]
    int*   ri = (int*)(sm + SM_B + 2048);  // [64][32]
    #pragma unroll
    for (int s = 0; s < 4; ++s) {
        int row  = wm * 32 + (s >> 1) * 16 + (lane >> 2) + (s & 1) * 8;
        int base = row * 32 + (wn * 4 + (lane & 3)) * 2;
        rv[base] = v1[s]; ri[base] = i1[s];
        rv[base + 1] = v2[s]; ri[base + 1] = i2[s];
    }
    __syncthreads();
    // per-token top-6 by lex (v, idx)
    if (tid < MT) {
        #pragma unroll
        for (int j = 0; j < 6; ++j) {
            float bv = CUDART_INF_F; int bi = 0x7fffffff, bk = 0;
            for (int k = 0; k < 32; ++k) {
                float v = rv[tid * 32 + k]; int ix = ri[tid * 32 + k];
                if (v < bv || (v == bv && ix < bi)) { bv = v; bi = ix; bk = k; }
            }
            rv[tid * 32 + bk] = CUDART_INF_F;
            ri[tid * 32 + bk] = 0x7fffffff;
            g_ci[(size_t)(tok0 + tid) * 8 + j] = bi;
        }
    }
}

// -------- exact fp32 rescore of 6 candidates/token (reference semantics) --------
__global__ void k_rescore(const float* __restrict__ x, const float* __restrict__ emb) {
    int t = blockIdx.x * 8 + (threadIdx.x >> 5);
    int lane = threadIdx.x & 31;
    const float* xr = x + (size_t)t * DIMK;
    float xl[8];
    #pragma unroll
    for (int i = 0; i < 8; ++i) xl[i] = xr[lane + i * 32];
    float x2v = g_x2[t];
    float bv = CUDART_INF_F; int bi = 0x7fffffff;
    #pragma unroll
    for (int j = 0; j < 6; ++j) {
        int c = g_ci[(size_t)t * 8 + j];
        const float* er = emb + (size_t)c * DIMK;
        float s = 0.f;
        #pragma unroll
        for (int i = 0; i < 8; ++i) s = fmaf(xl[i], er[lane + i * 32], s);
        #pragma unroll
        for (int o = 16; o; o >>= 1) s += __shfl_xor_sync(~0u, s, o);
        float d2 = fmaf(-2.0f, s, x2v + g_e2[c]);     // exact reference expression
        if (d2 < bv || (d2 == bv && c < bi)) { bv = d2; bi = c; }
    }
    if (lane == 0) g_idx[t] = bi;
}

// -------------------- gather + ST output + loss partials --------------------
__global__ void k_out(const float* __restrict__ x, const float* __restrict__ emb,
                      float* __restrict__ out) {
    int e4 = blockIdx.x * NTHR + threadIdx.x;
    int tok = e4 >> 6;
    float4 xv = ((const float4*)x)[e4];
    float4 qv = ((const float4*)emb)[(size_t)g_idx[tok] * 64 + (e4 & 63)];
    float dx = qv.x - xv.x, dy = qv.y - xv.y, dz = qv.z - xv.z, dw = qv.w - xv.w;
    float4 ov = {xv.x + dx, xv.y + dy, xv.z + dz, xv.w + dw};
    ((float4*)out)[e4] = ov;
    float s = fmaf(dx, dx, fmaf(dy, dy, fmaf(dz, dz, dw * dw)));
    #pragma unroll
    for (int o = 16; o; o >>= 1) s += __shfl_xor_sync(~0u, s, o);
    __shared__ float ws[8];
    if ((threadIdx.x & 31) == 0) ws[threadIdx.x >> 5] = s;
    __syncthreads();
    if (threadIdx.x == 0) {
        float b = ws[0];
        #pragma unroll
        for (int w = 1; w < 8; ++w) b += ws[w];
        g_partial[blockIdx.x] = b;
    }
}

__global__ void k_loss(float* __restrict__ out, int N, int nP) {
    __shared__ float s2[256];
    float s = 0.f;
    for (int i = threadIdx.x; i < nP; i += 256) s += g_partial[i];
    s2[threadIdx.x] = s;
    __syncthreads();
    #pragma unroll
    for (int st = 128; st; st >>= 1) {
        if (threadIdx.x < st) s2[threadIdx.x] += s2[threadIdx.x + st];
        __syncthreads();
    }
    if (threadIdx.x == 0) { float m = s2[0] / (float)N; out[N] = m + 0.25f * m; }
}

// ---------------------------------------------------------------------------
extern "C" void kernel_launch(void* const* d_in, const int* in_sizes, int n_in,
                              void* d_out, int out_size) {
    const float* x   = (const float*)d_in[0];
    const float* emb = (const float*)d_in[1];
    float* out = (float*)d_out;
    const int N = NT * DIMK;

    static bool init = false;
    if (!init) {
        cudaFuncSetAttribute(k_gemm, cudaFuncAttributeMaxDynamicSharedMemorySize,
                             SMEMF * 4);
        init = true;
    }
    k_e2<<<NV / 8, NTHR>>>(emb);
    k_x2<<<NT / 8, NTHR>>>(x);
    k_bsplit<<<NV * DIMK / NTHR, NTHR>>>(emb);
    k_gemm<<<NT / MT, NTHR, SMEMF * 4>>>(x);
    k_rescore<<<NT / 8, NTHR>>>(x, emb);
    k_out<<<N / 4 / NTHR, NTHR>>>(x, emb, out);
    k_loss<<<1, 256>>>(out, N, N / 4 / NTHR);
}

// round 8
// speedup vs baseline: 3.3552x; 1.0084x over previous
#include <cuda_runtime.h>
#include <math_constants.h>
#include <cstdint>

#define DIMK  256
#define NV    4096
#define NT    65536
#define MT    64           // tokens per block
#define NTHR  256

// smem layout (float offsets) — 112 KB total => 2 CTAs/SM (224 KB < 228 KB)
#define SM_E2  0           // 4096 floats
#define SM_A   4096        // 16384 floats (A tf32, fragment lane order)
#define SM_B   20480       // 2 stages x 4096 floats (tf32 B, paired-fragment order)
#define SMEMF  28672       // 114688 bytes

__device__ float g_e2[NV];
__device__ float g_x2[NT];
__device__ float g_partial[16384];
__device__ float g_bh[NV * DIMK];     // emb tf32, paired fragment order
__device__ int   g_ci[NT * 8];        // top-6 candidates per token (padded to 8)

__device__ __forceinline__ uint32_t s2u(const void* p) {
    uint32_t a;
    asm("{ .reg .u64 t; cvta.to.shared.u64 t, %1; cvt.u32.u64 %0, t; }" : "=r"(a) : "l"(p));
    return a;
}
__device__ __forceinline__ float tf32r(float a) {
    uint32_t u; asm("cvt.rna.tf32.f32 %0, %1;" : "=r"(u) : "f"(a));
    return __uint_as_float(u);
}
__device__ __forceinline__ void cp16(uint32_t d, const void* s) {
    asm volatile("cp.async.cg.shared.global [%0], [%1], 16;" :: "r"(d), "l"(s));
}
#define CP_COMMIT() asm volatile("cp.async.commit_group;" ::: "memory")
#define CP_WAIT1()  asm volatile("cp.async.wait_group 1;" ::: "memory")
#define CP_WAIT0()  asm volatile("cp.async.wait_group 0;" ::: "memory")

#define MMA(c, a, b) asm volatile(                                         \
    "mma.sync.aligned.m16n8k8.row.col.f32.tf32.tf32.f32 "                  \
    "{%0,%1,%2,%3}, {%4,%5,%6,%7}, {%8,%9}, {%0,%1,%2,%3};"                \
    : "+f"((c)[0]), "+f"((c)[1]), "+f"((c)[2]), "+f"((c)[3])               \
    : "r"((a)[0]), "r"((a)[1]), "r"((a)[2]), "r"((a)[3]),                  \
      "r"((b)[0]), "r"((b)[1]))

// -------------------- row sums of squares --------------------
__global__ void k_e2(const float* __restrict__ emb) {
    int w = (blockIdx.x * blockDim.x + threadIdx.x) >> 5, l = threadIdx.x & 31;
    if (w >= NV) return;
    const float* r = emb + (size_t)w * DIMK;
    float s = 0.f;
    #pragma unroll
    for (int i = 0; i < 8; ++i) { float v = r[l + i * 32]; s = fmaf(v, v, s); }
    #pragma unroll
    for (int o = 16; o; o >>= 1) s += __shfl_xor_sync(~0u, s, o);
    if (l == 0) g_e2[w] = s;
}
__global__ void k_x2(const float* __restrict__ x) {
    int w = (blockIdx.x * blockDim.x + threadIdx.x) >> 5, l = threadIdx.x & 31;
    if (w >= NT) return;
    const float* r = x + (size_t)w * DIMK;
    float s = 0.f;
    #pragma unroll
    for (int i = 0; i < 8; ++i) { float v = r[l + i * 32]; s = fmaf(v, v, s); }
    #pragma unroll
    for (int o = 16; o; o >>= 1) s += __shfl_xor_sync(~0u, s, o);
    if (l == 0) g_x2[w] = s;
}

// ---- pre-convert emb to tf32, PAIRED fragment order (LDS.128 per fn-pair) ----
// pos = ((nt*8+kc)*4+ks)*8 + wn*2 + (fl>>1)         [8192 blocks of 128 floats]
// within block: lane*4 + (fl&1)*2 + reg,  lane=((n&7)<<2)|(k&3), reg=(k>>2)&1
__global__ void k_bsplit(const float* __restrict__ emb) {
    int i = blockIdx.x * NTHR + threadIdx.x;
    int n = i >> 8, k = i & 255;
    float h = tf32r(emb[i]);
    int nl = n & 127, fg = nl >> 3;              // fragment group 0..15
    int wn = fg >> 2, fl = fg & 3;
    int pos = (((n >> 7) * 8 + (k >> 5)) * 4 + ((k >> 3) & 3)) * 8 + wn * 2 + (fl >> 1);
    int dst = pos * 128 + ((((n & 7) << 2) | (k & 3)) << 2) + ((fl & 1) << 1) + ((k >> 2) & 1);
    g_bh[dst] = h;
}

// ------------- main: tf32 mma ranking GEMM + top-2/thread + top-6/token -------------
__global__ void __launch_bounds__(NTHR, 2)
k_gemm(const float* __restrict__ x) {
    extern __shared__ float sm[];
    const int tid = threadIdx.x, lane = tid & 31, wid = tid >> 5;
    const int wm = wid >> 2, wn = wid & 3;
    const int tok0 = blockIdx.x * MT;
    const uint32_t sb = s2u(sm);

    for (int i = tid; i < NV; i += NTHR) sm[SM_E2 + i] = g_e2[i];

    // A -> smem as tf32, mma-A-fragment lane order
    for (int f = tid; f < MT * DIMK / 4; f += NTHR) {
        int m = f >> 6, k0 = (f & 63) << 2;
        float4 v = *(const float4*)(x + (size_t)(tok0 + m) * DIMK + k0);
        float vv[4] = {v.x, v.y, v.z, v.w};
        #pragma unroll
        for (int j = 0; j < 4; ++j) {
            int kk = k0 + j;
            int slot = (kk >> 3) * 4 + (m >> 4);
            int r = m & 15;
            int ln = ((r & 7) << 2) | (kk & 3);
            int rg = ((r >> 3) & 1) | (((kk >> 2) & 1) << 1);
            sm[SM_A + slot * 128 + ln * 4 + rg] = tf32r(vv[j]);
        }
    }
    __syncthreads();

    float v1[4], v2[4]; int i1[4], i2[4];
    #pragma unroll
    for (int s = 0; s < 4; ++s) {
        v1[s] = CUDART_INF_F; v2[s] = CUDART_INF_F;
        i1[s] = 0x7fffffff;   i2[s] = 0x7fffffff;
    }

    // prefetch stage 0
    {
        uint32_t db = sb + SM_B * 4;
        for (int t2 = tid; t2 < 1024; t2 += NTHR) cp16(db + t2 * 16, g_bh + t2 * 4);
        CP_COMMIT();
    }

    float C[2][4][4];

    for (int id = 0; id < 256; ++id) {          // id = nt*8 + kc
        const int buf = id & 1, kc = id & 7;
        if (kc == 0) {
            #pragma unroll
            for (int a = 0; a < 2; ++a)
                #pragma unroll
                for (int b = 0; b < 4; ++b)
                    #pragma unroll
                    for (int q = 0; q < 4; ++q) C[a][b][q] = 0.f;
        }
        if (id + 1 < 256) {
            const float* sh = g_bh + (size_t)(id + 1) * 4096;
            uint32_t db = sb + (SM_B + (buf ^ 1) * 4096) * 4;
            for (int t2 = tid; t2 < 1024; t2 += NTHR) cp16(db + t2 * 16, sh + t2 * 4);
            CP_COMMIT();
            CP_WAIT1();
        } else {
            CP_WAIT0();
        }
        __syncthreads();

        const float* bs = sm + SM_B + buf * 4096;

        // 1-deep register pipeline over ks: load(ks+1) overlaps MMA(ks)
        uint32_t ah[2][2][4], bf[2][4][2];
        #define LOADFRAG(KS, D) do {                                            \
            _Pragma("unroll")                                                   \
            for (int fm = 0; fm < 2; ++fm) {                                    \
                int slot = (kc * 4 + (KS)) * 4 + wm * 2 + fm;                   \
                float4 ra = *(const float4*)&sm[SM_A + slot * 128 + lane * 4];  \
                ah[D][fm][0] = __float_as_uint(ra.x);                           \
                ah[D][fm][1] = __float_as_uint(ra.y);                           \
                ah[D][fm][2] = __float_as_uint(ra.z);                           \
                ah[D][fm][3] = __float_as_uint(ra.w);                           \
            }                                                                   \
            _Pragma("unroll")                                                   \
            for (int pp = 0; pp < 2; ++pp) {                                    \
                int off = ((KS) * 8 + wn * 2 + pp) * 128 + lane * 4;            \
                float4 rb = *(const float4*)&bs[off];                           \
                bf[D][pp * 2 + 0][0] = __float_as_uint(rb.x);                   \
                bf[D][pp * 2 + 0][1] = __float_as_uint(rb.y);                   \
                bf[D][pp * 2 + 1][0] = __float_as_uint(rb.z);                   \
                bf[D][pp * 2 + 1][1] = __float_as_uint(rb.w);                   \
            }                                                                   \
        } while (0)

        LOADFRAG(0, 0);
        #pragma unroll
        for (int ks = 0; ks < 4; ++ks) {
            const int cur = ks & 1;
            if (ks < 3) {
                if (cur == 0) LOADFRAG(ks + 1, 1); else LOADFRAG(ks + 1, 0);
            }
            #pragma unroll
            for (int fm = 0; fm < 2; ++fm)
                #pragma unroll
                for (int fn = 0; fn < 4; ++fn) MMA(C[fm][fn], ah[cur][fm], bf[cur][fn]);
        }
        #undef LOADFRAG

        if (kc == 7) {
            // ranking value: e2[c] - 2*xe (x2 constant per row); cols ascending
            const int nt = id >> 3;
            #pragma unroll
            for (int fn = 0; fn < 4; ++fn) {
                float2 e2p = *(const float2*)&sm[SM_E2 + nt * 128 + wn * 32 + fn * 8
                                                 + (lane & 3) * 2];
                int col0 = nt * 128 + wn * 32 + fn * 8 + (lane & 3) * 2;
                #pragma unroll
                for (int fm = 0; fm < 2; ++fm)
                    #pragma unroll
                    for (int qh = 0; qh < 2; ++qh) {
                        int s = (fm << 1) | qh;
                        float d0 = fmaf(-2.0f, C[fm][fn][qh * 2 + 0], e2p.x);
                        float d1 = fmaf(-2.0f, C[fm][fn][qh * 2 + 1], e2p.y);
                        if (d0 < v1[s]) { v2[s] = v1[s]; i2[s] = i1[s]; v1[s] = d0; i1[s] = col0; }
                        else if (d0 < v2[s]) { v2[s] = d0; i2[s] = col0; }
                        if (d1 < v1[s]) { v2[s] = v1[s]; i2[s] = i1[s]; v1[s] = d1; i1[s] = col0 + 1; }
                        else if (d1 < v2[s]) { v2[s] = d1; i2[s] = col0 + 1; }
                    }
            }
        }
        __syncthreads();
    }

    // dump per-thread top-2 (16 contributors x 2 per token) into smem (reuse B region)
    float* rv = sm + SM_B;                 // [64][32]
    int*   ri = (int*)(sm + SM_B + 2048);  // [64][32]
    #pragma unroll
    for (int s = 0; s < 4; ++s) {
        int row  = wm * 32 + (s >> 1) * 16 + (lane >> 2) + (s & 1) * 8;
        int base = row * 32 + (wn * 4 + (lane & 3)) * 2;
        rv[base] = v1[s]; ri[base] = i1[s];
        rv[base + 1] = v2[s]; ri[base + 1] = i2[s];
    }
    __syncthreads();
    // per-token top-6 by lex (v, idx)
    if (tid < MT) {
        #pragma unroll
        for (int j = 0; j < 6; ++j) {
            float bv = CUDART_INF_F; int bi = 0x7fffffff, bk = 0;
            for (int k = 0; k < 32; ++k) {
                float v = rv[tid * 32 + k]; int ix = ri[tid * 32 + k];
                if (v < bv || (v == bv && ix < bi)) { bv = v; bi = ix; bk = k; }
            }
            rv[tid * 32 + bk] = CUDART_INF_F;
            ri[tid * 32 + bk] = 0x7fffffff;
            g_ci[(size_t)(tok0 + tid) * 8 + j] = bi;
        }
    }
}

// -------- fused: exact fp32 rescore (6 cands) + ST output + loss partial --------
__global__ void k_quant(const float* __restrict__ x, const float* __restrict__ emb,
                        float* __restrict__ out) {
    int wid = threadIdx.x >> 5, lane = threadIdx.x & 31;
    int t = blockIdx.x * 8 + wid;
    const float* xr = x + (size_t)t * DIMK;
    float xl[8];
    #pragma unroll
    for (int i = 0; i < 8; ++i) xl[i] = xr[lane + i * 32];
    float x2v = g_x2[t];
    float bv = CUDART_INF_F; int bi = 0x7fffffff;
    #pragma unroll
    for (int j = 0; j < 6; ++j) {
        int c = g_ci[(size_t)t * 8 + j];
        const float* er = emb + (size_t)c * DIMK;
        float s = 0.f;
        #pragma unroll
        for (int i = 0; i < 8; ++i) s = fmaf(xl[i], er[lane + i * 32], s);
        #pragma unroll
        for (int o = 16; o; o >>= 1) s += __shfl_xor_sync(~0u, s, o);
        float d2 = fmaf(-2.0f, s, x2v + g_e2[c]);     // exact reference expression
        if (d2 < bv || (d2 == bv && c < bi)) { bv = d2; bi = c; }
    }
    // bi identical across lanes (butterfly gave all lanes the full sum)
    const float* er = emb + (size_t)bi * DIMK;
    float* orow = out + (size_t)t * DIMK;
    float part = 0.f;
    #pragma unroll
    for (int i = 0; i < 8; ++i) {
        float q = er[lane + i * 32];
        float d = q - xl[i];
        orow[lane + i * 32] = xl[i] + d;              // exact ST expression
        part = fmaf(d, d, part);
    }
    #pragma unroll
    for (int o = 16; o; o >>= 1) part += __shfl_xor_sync(~0u, part, o);
    __shared__ float ws[8];
    if (lane == 0) ws[wid] = part;
    __syncthreads();
    if (threadIdx.x == 0) {
        float b = ws[0];
        #pragma unroll
        for (int w = 1; w < 8; ++w) b += ws[w];
        g_partial[blockIdx.x] = b;
    }
}

__global__ void k_loss(float* __restrict__ out, int N, int nP) {
    __shared__ float s2[256];
    float s = 0.f;
    for (int i = threadIdx.x; i < nP; i += 256) s += g_partial[i];
    s2[threadIdx.x] = s;
    __syncthreads();
    #pragma unroll
    for (int st = 128; st; st >>= 1) {
        if (threadIdx.x < st) s2[threadIdx.x] += s2[threadIdx.x + st];
        __syncthreads();
    }
    if (threadIdx.x == 0) { float m = s2[0] / (float)N; out[N] = m + 0.25f * m; }
}

// ---------------------------------------------------------------------------
extern "C" void kernel_launch(void* const* d_in, const int* in_sizes, int n_in,
                              void* d_out, int out_size) {
    const float* x   = (const float*)d_in[0];
    const float* emb = (const float*)d_in[1];
    float* out = (float*)d_out;
    const int N = NT * DIMK;

    static bool init = false;
    if (!init) {
        cudaFuncSetAttribute(k_gemm, cudaFuncAttributeMaxDynamicSharedMemorySize,
                             SMEMF * 4);
        init = true;
    }
    k_e2<<<NV / 8, NTHR>>>(emb);
    k_x2<<<NT / 8, NTHR>>>(x);
    k_bsplit<<<NV * DIMK / NTHR, NTHR>>>(emb);
    k_gemm<<<NT / MT, NTHR, SMEMF * 4>>>(x);
    k_quant<<<NT / 8, NTHR>>>(x, emb, out);
    k_loss<<<1, 256>>>(out, N, NT / 8);
}

// round 9
// speedup vs baseline: 5.9856x; 1.7840x over previous
#include <cuda_runtime.h>
#include <math_constants.h>
#include <cstdint>

#define DIMK  256
#define NV    4096
#define NT    65536
#define MT    64           // tokens per k_gemm CTA
#define NTHR  256          // aux kernels
#define GTHR  128          // k_gemm threads (4 warps: 1M x 4N)

__device__ float    g_e2[NV];
__device__ float    g_partial[8192];
__device__ unsigned g_ah[NT * DIMK / 2];   // x  bf16x2, A-fragment order
__device__ unsigned g_bh[NV * DIMK / 2];   // emb bf16x2, B-fragment order (paired)
__device__ int      g_ci[NT * 8];          // top-8 candidates per token

__device__ __forceinline__ uint32_t s2u(const void* p) {
    uint32_t a;
    asm("{ .reg .u64 t; cvta.to.shared.u64 t, %1; cvt.u32.u64 %0, t; }" : "=r"(a) : "l"(p));
    return a;
}
__device__ __forceinline__ unsigned bf2(float lo, float hi) {
    unsigned r;
    asm("cvt.rn.bf16x2.f32 %0, %1, %2;" : "=r"(r) : "f"(hi), "f"(lo));  // hi goes to upper
    return r;
}
__device__ __forceinline__ void cp16(uint32_t d, const void* s) {
    asm volatile("cp.async.cg.shared.global [%0], [%1], 16;" :: "r"(d), "l"(s));
}
#define CP_COMMIT() asm volatile("cp.async.commit_group;" ::: "memory")
#define CP_WAIT1()  asm volatile("cp.async.wait_group 1;" ::: "memory")
#define CP_WAIT0()  asm volatile("cp.async.wait_group 0;" ::: "memory")

// bf16 m16n8k16 MMA, fp32 accumulate
#define MMAB(c, a, b0, b1) asm volatile(                                    \
    "mma.sync.aligned.m16n8k16.row.col.f32.bf16.bf16.f32 "                  \
    "{%0,%1,%2,%3}, {%4,%5,%6,%7}, {%8,%9}, {%0,%1,%2,%3};"                 \
    : "+f"((c)[0]), "+f"((c)[1]), "+f"((c)[2]), "+f"((c)[3])                \
    : "r"((a)[0]), "r"((a)[1]), "r"((a)[2]), "r"((a)[3]),                   \
      "r"(b0), "r"(b1))

// -------------------- e2[v] = sum emb[v,:]^2 --------------------
__global__ void k_e2(const float* __restrict__ emb) {
    int w = (blockIdx.x * blockDim.x + threadIdx.x) >> 5, l = threadIdx.x & 31;
    if (w >= NV) return;
    const float* r = emb + (size_t)w * DIMK;
    float s = 0.f;
    #pragma unroll
    for (int i = 0; i < 8; ++i) { float v = r[l + i * 32]; s = fmaf(v, v, s); }
    #pragma unroll
    for (int o = 16; o; o >>= 1) s += __shfl_xor_sync(~0u, s, o);
    if (l == 0) g_e2[w] = s;
}

// ---- x -> bf16x2 in A-fragment order (m16n8k16) ----
// i -> reg(2b) | lane(5b) | slot(6b) | blk : slot = kstep*4+fm
// row = blk*64 + fm*16 + (reg&1)*8 + (lane>>2); k0 = kstep*16 + (reg>>1)*8 + (lane&3)*2
__global__ void k_asplit(const float* __restrict__ x) {
    int i = blockIdx.x * NTHR + threadIdx.x;          // 8,388,608 uints
    int r = i & 3, lane = (i >> 2) & 31, slot = (i >> 7) & 63, blk = i >> 13;
    int kstep = slot >> 2, fm = slot & 3;
    int row = blk * 64 + fm * 16 + (r & 1) * 8 + (lane >> 2);
    int k0  = kstep * 16 + (r >> 1) * 8 + (lane & 3) * 2;
    const float* p = x + (size_t)row * DIMK + k0;
    g_ah[i] = bf2(p[0], p[1]);
}

// ---- emb -> bf16x2 in paired B-fragment order ----
// i -> q(2b) | lane(5b) | p(5b) | id(7b); p = (kl*4+wn)*2 + fpair
// fn = fpair*2 + (q>>1), breg = q&1; nt = id>>2, kc = id&3
// n = nt*128 + wn*32 + fn*8 + (lane>>2); k = kc*64 + kl*16 + breg*8 + (lane&3)*2
__global__ void k_bsplit(const float* __restrict__ emb) {
    int i = blockIdx.x * NTHR + threadIdx.x;          // 524,288 uints
    int q = i & 3, lane = (i >> 2) & 31, p = (i >> 7) & 31, id = i >> 12;
    int fpair = p & 1, pk = p >> 1, kl = pk >> 2, wn = pk & 3;
    int fn = fpair * 2 + (q >> 1), breg = q & 1;
    int nt = id >> 2, kc = id & 3;
    int n = nt * 128 + wn * 32 + fn * 8 + (lane >> 2);
    int k = kc * 64 + kl * 16 + breg * 8 + (lane & 3) * 2;
    const float* e = emb + (size_t)n * DIMK + k;
    g_bh[i] = bf2(e[0], e[1]);
}

// ------------- bf16 mma ranking GEMM + top-2/thread + top-8/token -------------
// 4 warps (wn=wid), warp tile 64 rows x 32 cols (fm<4, fn<4). 128 ids = nt*4+kc.
__global__ void __launch_bounds__(GTHR, 3)
k_gemm() {
    extern __shared__ unsigned sm[];                  // A: [0,8192) B: [8192,16384)
    const int tid = threadIdx.x, lane = tid & 31, wn = tid >> 5;
    const int tok0 = blockIdx.x * MT;
    const uint32_t sb = s2u(sm);

    // A (32KB) + B stage0 (16KB) via cp.async
    {
        const uint4* as = (const uint4*)g_ah + (size_t)blockIdx.x * 2048;
        #pragma unroll
        for (int i = 0; i < 16; ++i) cp16(sb + (tid + i * GTHR) * 16, as + tid + i * GTHR);
        const uint4* bs0 = (const uint4*)g_bh;
        #pragma unroll
        for (int i = 0; i < 8; ++i)
            cp16(sb + 32768 + (tid + i * GTHR) * 16, bs0 + tid + i * GTHR);
        CP_COMMIT();
    }

    float v1[8], v2[8]; int i1[8], i2[8];
    #pragma unroll
    for (int s = 0; s < 8; ++s) {
        v1[s] = CUDART_INF_F; v2[s] = CUDART_INF_F;
        i1[s] = 0x7fffffff;   i2[s] = 0x7fffffff;
    }

    float C[4][4][4];

    for (int id = 0; id < 128; ++id) {                // id = nt*4 + kc
        const int buf = id & 1, kc = id & 3;
        if (kc == 0) {
            #pragma unroll
            for (int a = 0; a < 4; ++a)
                #pragma unroll
                for (int b = 0; b < 4; ++b)
                    #pragma unroll
                    for (int q = 0; q < 4; ++q) C[a][b][q] = 0.f;
        }
        if (id + 1 < 128) {
            const uint4* bs = (const uint4*)g_bh + (size_t)(id + 1) * 1024;
            uint32_t db = sb + 32768 + (buf ^ 1) * 16384;
            #pragma unroll
            for (int i = 0; i < 8; ++i)
                cp16(db + (tid + i * GTHR) * 16, bs + tid + i * GTHR);
            CP_COMMIT();
            CP_WAIT1();
        } else {
            CP_WAIT0();
        }
        __syncthreads();

        const unsigned* bb = sm + 8192 + buf * 4096;
        #pragma unroll
        for (int kl = 0; kl < 4; ++kl) {
            unsigned ah[4][4];
            #pragma unroll
            for (int fm = 0; fm < 4; ++fm) {
                uint4 ra = *(const uint4*)&sm[((kc * 4 + kl) * 4 + fm) * 128 + lane * 4];
                ah[fm][0] = ra.x; ah[fm][1] = ra.y; ah[fm][2] = ra.z; ah[fm][3] = ra.w;
            }
            uint4 rb0 = *(const uint4*)&bb[((kl * 4 + wn) * 2 + 0) * 128 + lane * 4];
            uint4 rb1 = *(const uint4*)&bb[((kl * 4 + wn) * 2 + 1) * 128 + lane * 4];
            #pragma unroll
            for (int fm = 0; fm < 4; ++fm) {
                MMAB(C[fm][0], ah[fm], rb0.x, rb0.y);
                MMAB(C[fm][1], ah[fm], rb0.z, rb0.w);
                MMAB(C[fm][2], ah[fm], rb1.x, rb1.y);
                MMAB(C[fm][3], ah[fm], rb1.z, rb1.w);
            }
        }

        if (kc == 3) {
            // ranking value: e2[c] - 2*xe ; cols visited ascending per slot
            const int nt = id >> 2;
            #pragma unroll
            for (int fn = 0; fn < 4; ++fn) {
                int col0 = nt * 128 + wn * 32 + fn * 8 + (lane & 3) * 2;
                float2 e2p = __ldg((const float2*)&g_e2[col0]);
                #pragma unroll
                for (int fm = 0; fm < 4; ++fm)
                    #pragma unroll
                    for (int qh = 0; qh < 2; ++qh) {
                        int s = (fm << 1) | qh;
                        float d0 = fmaf(-2.0f, C[fm][fn][qh * 2 + 0], e2p.x);
                        float d1 = fmaf(-2.0f, C[fm][fn][qh * 2 + 1], e2p.y);
                        if (d0 < v1[s]) { v2[s] = v1[s]; i2[s] = i1[s]; v1[s] = d0; i1[s] = col0; }
                        else if (d0 < v2[s]) { v2[s] = d0; i2[s] = col0; }
                        if (d1 < v1[s]) { v2[s] = v1[s]; i2[s] = i1[s]; v1[s] = d1; i1[s] = col0 + 1; }
                        else if (d1 < v2[s]) { v2[s] = d1; i2[s] = col0 + 1; }
                    }
            }
        }
        __syncthreads();
    }

    // dump per-thread top-2: 16 contributors x 2 = 32 candidates per token
    float* rv = (float*)(sm + 8192);          // [64][32]
    int*   ri = (int*)(sm + 8192 + 2048);     // [64][32]
    #pragma unroll
    for (int s = 0; s < 8; ++s) {
        int row  = (s >> 1) * 16 + (s & 1) * 8 + (lane >> 2);
        int base = row * 32 + (wn * 4 + (lane & 3)) * 2;
        rv[base] = v1[s];     ri[base] = i1[s];
        rv[base + 1] = v2[s]; ri[base + 1] = i2[s];
    }
    __syncthreads();
    // per-token top-8 by lex (v, idx)
    if (tid < MT) {
        #pragma unroll
        for (int j = 0; j < 8; ++j) {
            float bv = CUDART_INF_F; int bi = 0x7fffffff, bk = 0;
            for (int k = 0; k < 32; ++k) {
                float v = rv[tid * 32 + k]; int ix = ri[tid * 32 + k];
                if (v < bv || (v == bv && ix < bi)) { bv = v; bi = ix; bk = k; }
            }
            rv[tid * 32 + bk] = CUDART_INF_F;
            ri[tid * 32 + bk] = 0x7fffffff;
            g_ci[(size_t)(tok0 + tid) * 8 + j] = bi;
        }
    }
}

// ---- fused: exact fp32 rescore (8 cands) + ST output + loss partial ----
__global__ void k_quant(const float* __restrict__ x, const float* __restrict__ emb,
                        float* __restrict__ out) {
    int wid = threadIdx.x >> 5, lane = threadIdx.x & 31;
    int t = blockIdx.x * 8 + wid;
    const float* xr = x + (size_t)t * DIMK;
    float xl[8];
    #pragma unroll
    for (int i = 0; i < 8; ++i) xl[i] = xr[lane + i * 32];
    float x2v = 0.f;
    #pragma unroll
    for (int i = 0; i < 8; ++i) x2v = fmaf(xl[i], xl[i], x2v);
    #pragma unroll
    for (int o = 16; o; o >>= 1) x2v += __shfl_xor_sync(~0u, x2v, o);

    float bv = CUDART_INF_F; int bi = 0x7fffffff;
    #pragma unroll
    for (int j = 0; j < 8; ++j) {
        int c = g_ci[(size_t)t * 8 + j];
        const float* er = emb + (size_t)c * DIMK;
        float s = 0.f;
        #pragma unroll
        for (int i = 0; i < 8; ++i) s = fmaf(xl[i], er[lane + i * 32], s);
        #pragma unroll
        for (int o = 16; o; o >>= 1) s += __shfl_xor_sync(~0u, s, o);
        float d2 = fmaf(-2.0f, s, x2v + g_e2[c]);      // exact reference expression
        if (d2 < bv || (d2 == bv && c < bi)) { bv = d2; bi = c; }
    }
    const float* er = emb + (size_t)bi * DIMK;
    float* orow = out + (size_t)t * DIMK;
    float part = 0.f;
    #pragma unroll
    for (int i = 0; i < 8; ++i) {
        float q = er[lane + i * 32];
        float d = q - xl[i];
        orow[lane + i * 32] = xl[i] + d;               // exact ST expression
        part = fmaf(d, d, part);
    }
    #pragma unroll
    for (int o = 16; o; o >>= 1) part += __shfl_xor_sync(~0u, part, o);
    __shared__ float ws[8];
    if (lane == 0) ws[wid] = part;
    __syncthreads();
    if (threadIdx.x == 0) {
        float b = ws[0];
        #pragma unroll
        for (int w = 1; w < 8; ++w) b += ws[w];
        g_partial[blockIdx.x] = b;
    }
}

__global__ void k_loss(float* __restrict__ out, int N, int nP) {
    __shared__ float s2[256];
    float s = 0.f;
    for (int i = threadIdx.x; i < nP; i += 256) s += g_partial[i];
    s2[threadIdx.x] = s;
    __syncthreads();
    #pragma unroll
    for (int st = 128; st; st >>= 1) {
        if (threadIdx.x < st) s2[threadIdx.x] += s2[threadIdx.x + st];
        __syncthreads();
    }
    if (threadIdx.x == 0) { float m = s2[0] / (float)N; out[N] = m + 0.25f * m; }
}

// ---------------------------------------------------------------------------
extern "C" void kernel_launch(void* const* d_in, const int* in_sizes, int n_in,
                              void* d_out, int out_size) {
    const float* x   = (const float*)d_in[0];
    const float* emb = (const float*)d_in[1];
    float* out = (float*)d_out;
    const int N = NT * DIMK;
    const int GSMEM = 16384 * 4;                      // 64 KB

    static bool init = false;
    if (!init) {
        cudaFuncSetAttribute(k_gemm, cudaFuncAttributeMaxDynamicSharedMemorySize, GSMEM);
        init = true;
    }
    k_e2<<<NV / 8, NTHR>>>(emb);
    k_bsplit<<<NV * DIMK / 2 / NTHR, NTHR>>>(emb);
    k_asplit<<<NT * DIMK / 2 / NTHR, NTHR>>>(x);
    k_gemm<<<NT / MT, GTHR, GSMEM>>>();
    k_quant<<<NT / 8, NTHR>>>(x, emb, out);
    k_loss<<<1, 256>>>(out, N, NT / 8);
}

// round 10
// speedup vs baseline: 8.2012x; 1.3702x over previous
#include <cuda_runtime.h>
#include <math_constants.h>
#include <cstdint>

#define DIMK  256
#define NV    4096
#define NT    65536
#define MT    64           // tokens per k_gemm CTA
#define NTHR  256          // aux kernels
#define GTHR  128          // k_gemm threads (4 warps, each = one 32-col N slice)

__device__ float    g_e2[NV];
__device__ float    g_partial[8192];
__device__ unsigned g_ah[NT * DIMK / 2];   // x  bf16x2, A-fragment order
__device__ unsigned g_bh[NV * DIMK / 2];   // emb bf16x2, per-(step,warp,lane) order
__device__ int      g_ci[NT * 8];          // top-8 candidates per token

__device__ __forceinline__ uint32_t s2u(const void* p) {
    uint32_t a;
    asm("{ .reg .u64 t; cvta.to.shared.u64 t, %1; cvt.u32.u64 %0, t; }" : "=r"(a) : "l"(p));
    return a;
}
__device__ __forceinline__ unsigned bf2(float lo, float hi) {
    unsigned r;
    asm("cvt.rn.bf16x2.f32 %0, %1, %2;" : "=r"(r) : "f"(hi), "f"(lo));
    return r;
}
__device__ __forceinline__ void cp16(uint32_t d, const void* s) {
    asm volatile("cp.async.cg.shared.global [%0], [%1], 16;" :: "r"(d), "l"(s));
}
#define CP_COMMIT() asm volatile("cp.async.commit_group;" ::: "memory")
#define CP_WAIT3()  asm volatile("cp.async.wait_group 3;" ::: "memory")

#define MMAB(c, a, b0, b1) asm volatile(                                    \
    "mma.sync.aligned.m16n8k16.row.col.f32.bf16.bf16.f32 "                  \
    "{%0,%1,%2,%3}, {%4,%5,%6,%7}, {%8,%9}, {%0,%1,%2,%3};"                 \
    : "+f"((c)[0]), "+f"((c)[1]), "+f"((c)[2]), "+f"((c)[3])                \
    : "r"((a)[0]), "r"((a)[1]), "r"((a)[2]), "r"((a)[3]),                   \
      "r"(b0), "r"(b1))

// monotone uint mapping of float (total order matching <)
__device__ __forceinline__ unsigned fmono(float f) {
    unsigned u = __float_as_uint(f);
    return u ^ (0x80000000u | (unsigned)((int)u >> 31));
}

// -------------------- e2[v] = sum emb[v,:]^2 --------------------
__global__ void k_e2(const float* __restrict__ emb) {
    int w = (blockIdx.x * blockDim.x + threadIdx.x) >> 5, l = threadIdx.x & 31;
    if (w >= NV) return;
    const float* r = emb + (size_t)w * DIMK;
    float s = 0.f;
    #pragma unroll
    for (int i = 0; i < 8; ++i) { float v = r[l + i * 32]; s = fmaf(v, v, s); }
    #pragma unroll
    for (int o = 16; o; o >>= 1) s += __shfl_xor_sync(~0u, s, o);
    if (l == 0) g_e2[w] = s;
}

// ---- x -> bf16x2 in A-fragment order (m16n8k16), unchanged from r9 ----
__global__ void k_asplit(const float* __restrict__ x) {
    int i = blockIdx.x * NTHR + threadIdx.x;
    int r = i & 3, lane = (i >> 2) & 31, slot = (i >> 7) & 63, blk = i >> 13;
    int kstep = slot >> 2, fm = slot & 3;
    int row = blk * 64 + fm * 16 + (r & 1) * 8 + (lane >> 2);
    int k0  = kstep * 16 + (r >> 1) * 8 + (lane & 3) * 2;
    const float* p = x + (size_t)row * DIMK + k0;
    g_ah[i] = bf2(p[0], p[1]);
}

// ---- emb -> bf16x2, per-(step, warp, lane) self-read order ----
// i = ((((step*4 + wn)*2 + part)*32 + lane)*4) + fhalf*2 + breg
// step = nt*16 + kc*4 + kl ; fn = part*2 + fhalf
// n = nt*128 + wn*32 + fn*8 + (lane>>2) ; k = kc*64 + kl*16 + breg*8 + (lane&3)*2
__global__ void k_bsplit(const float* __restrict__ emb) {
    int i = blockIdx.x * NTHR + threadIdx.x;          // 524,288 uints
    int breg = i & 1, fhalf = (i >> 1) & 1, lane = (i >> 2) & 31;
    int part = (i >> 7) & 1, wn = (i >> 8) & 3, step = i >> 10;
    int kl = step & 3, kc = (step >> 2) & 3, nt = step >> 4;
    int n = nt * 128 + wn * 32 + (part * 2 + fhalf) * 8 + (lane >> 2);
    int k = kc * 64 + kl * 16 + breg * 8 + (lane & 3) * 2;
    const float* e = emb + (size_t)n * DIMK + k;
    g_bh[i] = bf2(e[0], e[1]);
}

// ------- barrier-free bf16 ranking GEMM: warp-private B ring, packed keys -------
__global__ void __launch_bounds__(GTHR, 4)
k_gemm() {
    extern __shared__ unsigned sm[];   // A: [0,8192) ; B rings: [8192 + wn*1024, +1024)
    const int tid = threadIdx.x, lane = tid & 31, wn = tid >> 5;
    const int tok0 = blockIdx.x * MT;
    const uint32_t sb = s2u(sm);
    const uint32_t bring = sb + 32768 + wn * 4096;    // bytes

    // A tile (2048 uint4) via cp.async, group 0
    {
        const uint4* as = (const uint4*)g_ah + (size_t)blockIdx.x * 2048;
        #pragma unroll
        for (int i = 0; i < 16; ++i)
            cp16(sb + (tid + i * GTHR) * 16, as + tid + i * GTHR);
        CP_COMMIT();
    }

    // warp-private B prefetch: lane loads exactly the 2 uint4 it will read
    #define BPRE(S) do {                                                        \
        const uint4* _s = (const uint4*)g_bh + ((size_t)(S) * 4 + wn) * 64 + lane; \
        uint32_t _d = bring + ((S) & 3) * 1024 + lane * 16;                     \
        cp16(_d, _s); cp16(_d + 512, _s + 32); } while (0)

    BPRE(0); CP_COMMIT();
    BPRE(1); CP_COMMIT();
    BPRE(2); CP_COMMIT();
    CP_WAIT3();            // group 0 (A) complete
    __syncthreads();       // A visible to all warps — the ONLY CTA barrier before merge

    unsigned k1[8], k2[8];
    #pragma unroll
    for (int s = 0; s < 8; ++s) { k1[s] = 0xFFFFFFFFu; k2[s] = 0xFFFFFFFFu; }

    float C[4][4][4];

    for (int nt = 0; nt < 32; ++nt) {
        #pragma unroll
        for (int a = 0; a < 4; ++a)
            #pragma unroll
            for (int b = 0; b < 4; ++b)
                #pragma unroll
                for (int q = 0; q < 4; ++q) C[a][b][q] = 0.f;

        #pragma unroll 4
        for (int ks = 0; ks < 16; ++ks) {
            const int step = nt * 16 + ks;
            if (step + 3 < 512) BPRE(step + 3);
            CP_COMMIT();                              // empty group OK in tail
            CP_WAIT3();                               // step's B ready (self-read)

            unsigned ah[4][4];
            #pragma unroll
            for (int fm = 0; fm < 4; ++fm) {
                uint4 ra = *(const uint4*)&sm[(ks * 4 + fm) * 128 + lane * 4];
                ah[fm][0] = ra.x; ah[fm][1] = ra.y; ah[fm][2] = ra.z; ah[fm][3] = ra.w;
            }
            const unsigned* bst = sm + 8192 + wn * 1024 + (step & 3) * 256;
            uint4 rb0 = *(const uint4*)&bst[lane * 4];
            uint4 rb1 = *(const uint4*)&bst[128 + lane * 4];
            #pragma unroll
            for (int fm = 0; fm < 4; ++fm) {
                MMAB(C[fm][0], ah[fm], rb0.x, rb0.y);
                MMAB(C[fm][1], ah[fm], rb0.z, rb0.w);
                MMAB(C[fm][2], ah[fm], rb1.x, rb1.y);
                MMAB(C[fm][3], ah[fm], rb1.z, rb1.w);
            }
        }

        // epilogue: packed keys (chopped monotone d | col), top-2 via IMNMX
        #pragma unroll
        for (int fn = 0; fn < 4; ++fn) {
            unsigned col0 = nt * 128 + wn * 32 + fn * 8 + (lane & 3) * 2;
            float2 e2p = __ldg((const float2*)&g_e2[col0]);
            #pragma unroll
            for (int fm = 0; fm < 4; ++fm)
                #pragma unroll
                for (int qh = 0; qh < 2; ++qh) {
                    int s = (fm << 1) | qh;
                    float d0 = fmaf(-2.0f, C[fm][fn][qh * 2 + 0], e2p.x);
                    float d1 = fmaf(-2.0f, C[fm][fn][qh * 2 + 1], e2p.y);
                    unsigned key0 = (fmono(d0) & 0xFFFFF000u) | col0;
                    unsigned key1 = (fmono(d1) & 0xFFFFF000u) | (col0 + 1);
                    unsigned lo = min(k1[s], key0), hi = max(k1[s], key0);
                    k1[s] = lo; k2[s] = min(k2[s], hi);
                    lo = min(k1[s], key1); hi = max(k1[s], key1);
                    k1[s] = lo; k2[s] = min(k2[s], hi);
                }
        }
    }

    // merge: 16 contributors x 2 keys per token -> top-8
    __syncthreads();                       // all warps done with B rings
    unsigned* rk = sm + 8192;              // [64][32] keys (reuse B region)
    #pragma unroll
    for (int s = 0; s < 8; ++s) {
        int row = (s >> 1) * 16 + (s & 1) * 8 + (lane >> 2);
        int c   = (wn * 4 + (lane & 3)) * 2;
        rk[row * 32 + c]     = k1[s];
        rk[row * 32 + c + 1] = k2[s];
    }
    __syncthreads();
    if (tid < MT) {
        #pragma unroll
        for (int j = 0; j < 8; ++j) {
            unsigned bk = 0xFFFFFFFFu; int bp = 0;
            for (int k = 0; k < 32; ++k) {
                unsigned v = rk[tid * 32 + k];
                if (v < bk) { bk = v; bp = k; }
            }
            rk[tid * 32 + bp] = 0xFFFFFFFFu;
            g_ci[(size_t)(tok0 + tid) * 8 + j] = (int)(bk & 0xFFFu);
        }
    }
    #undef BPRE
}

// ---- fused: exact fp32 rescore (8 cands) + ST output + loss partial ----
__global__ void k_quant(const float* __restrict__ x, const float* __restrict__ emb,
                        float* __restrict__ out) {
    int wid = threadIdx.x >> 5, lane = threadIdx.x & 31;
    int t = blockIdx.x * 8 + wid;
    const float* xr = x + (size_t)t * DIMK;
    float xl[8];
    #pragma unroll
    for (int i = 0; i < 8; ++i) xl[i] = xr[lane + i * 32];
    float x2v = 0.f;
    #pragma unroll
    for (int i = 0; i < 8; ++i) x2v = fmaf(xl[i], xl[i], x2v);
    #pragma unroll
    for (int o = 16; o; o >>= 1) x2v += __shfl_xor_sync(~0u, x2v, o);

    float bv = CUDART_INF_F; int bi = 0x7fffffff;
    #pragma unroll
    for (int j = 0; j < 8; ++j) {
        int c = g_ci[(size_t)t * 8 + j];
        const float* er = emb + (size_t)c * DIMK;
        float s = 0.f;
        #pragma unroll
        for (int i = 0; i < 8; ++i) s = fmaf(xl[i], er[lane + i * 32], s);
        #pragma unroll
        for (int o = 16; o; o >>= 1) s += __shfl_xor_sync(~0u, s, o);
        float d2 = fmaf(-2.0f, s, x2v + g_e2[c]);      // exact reference expression
        if (d2 < bv || (d2 == bv && c < bi)) { bv = d2; bi = c; }
    }
    const float* er = emb + (size_t)bi * DIMK;
    float* orow = out + (size_t)t * DIMK;
    float part = 0.f;
    #pragma unroll
    for (int i = 0; i < 8; ++i) {
        float q = er[lane + i * 32];
        float d = q - xl[i];
        orow[lane + i * 32] = xl[i] + d;               // exact ST expression
        part = fmaf(d, d, part);
    }
    #pragma unroll
    for (int o = 16; o; o >>= 1) part += __shfl_xor_sync(~0u, part, o);
    __shared__ float ws[8];
    if (lane == 0) ws[wid] = part;
    __syncthreads();
    if (threadIdx.x == 0) {
        float b = ws[0];
        #pragma unroll
        for (int w = 1; w < 8; ++w) b += ws[w];
        g_partial[blockIdx.x] = b;
    }
}

__global__ void k_loss(float* __restrict__ out, int N, int nP) {
    __shared__ float s2[256];
    float s = 0.f;
    for (int i = threadIdx.x; i < nP; i += 256) s += g_partial[i];
    s2[threadIdx.x] = s;
    __syncthreads();
    #pragma unroll
    for (int st = 128; st; st >>= 1) {
        if (threadIdx.x < st) s2[threadIdx.x] += s2[threadIdx.x + st];
        __syncthreads();
    }
    if (threadIdx.x == 0) { float m = s2[0] / (float)N; out[N] = m + 0.25f * m; }
}

// ---------------------------------------------------------------------------
extern "C" void kernel_launch(void* const* d_in, const int* in_sizes, int n_in,
                              void* d_out, int out_size) {
    const float* x   = (const float*)d_in[0];
    const float* emb = (const float*)d_in[1];
    float* out = (float*)d_out;
    const int N = NT * DIMK;
    const int GSMEM = 49152;                          // 32KB A + 16KB B rings

    static bool init = false;
    if (!init) {
        cudaFuncSetAttribute(k_gemm, cudaFuncAttributeMaxDynamicSharedMemorySize, GSMEM);
        init = true;
    }
    k_e2<<<NV / 8, NTHR>>>(emb);
    k_bsplit<<<NV * DIMK / 2 / NTHR, NTHR>>>(emb);
    k_asplit<<<NT * DIMK / 2 / NTHR, NTHR>>>(x);
    k_gemm<<<NT / MT, GTHR, GSMEM>>>();
    k_quant<<<NT / 8, NTHR>>>(x, emb, out);
    k_loss<<<1, 256>>>(out, N, NT / 8);
}